// round 16
// baseline (speedup 1.0000x reference)
#include <cuda_runtime.h>
#include <math.h>
#include <stdint.h>

#ifndef M_PI
#define M_PI 3.14159265358979323846
#endif

// Problem shape (fixed by setup_inputs)
#define BB 2
#define NV 4
#define HH 256
#define WW 512
#define HWSZ (HH * WW)            // 131072
#define PP (NV * HWSZ)            // 524288 points per batch
#define TOTAL (BB * PP)           // 1048576 points total
#define NCH 24

#define VOXEL_SIZE 0.1f
#define CONF_W 0.7f
#define OPAC_W 0.3f
#define CONF_THRESH 0.1f
#define OPAC_THRESH 0.01f

// Direct-mapped voxel window: vc in [448, 576) per axis covers |mean|<=6.4,
// far beyond the data's reach. Out-of-window points (practically never) fall
// back to a hash table appended after the direct region -> correct for ANY input.
#define WIN_LO 448
#define WIN_SZ 128
#define DIRECT_SLOTS (BB * WIN_SZ * WIN_SZ * WIN_SZ)   // 4.19M

#define TABLE_BITS 20
#define TABLE_SIZE (1u << TABLE_BITS)
#define TABLE_MASK (TABLE_SIZE - 1u)

#define NSLOTS (DIRECT_SLOTS + (int)TABLE_SIZE)

// Scratch (__device__ globals, zero-initialized at module load; cleanup
// restores the zero state after every launch so graph replays start clean).
__device__ ulonglong2    g_pair[NSLOTS];            // {max1, max2}, 0 = untouched
__device__ unsigned int  g_keys[TABLE_SIZE];        // fallback hash keys, 0 = empty
__device__ unsigned int  g_used[TOTAL];             // first-touched slot list
__device__ unsigned int  g_cnt;                     // #touched slots
__device__ unsigned int  g_done;                    // cleanup block counter

// ---------------------------------------------------------------------------

__device__ __forceinline__ unsigned hash_claim(unsigned key) {
    unsigned h = (key * 2654435761u) >> (32 - TABLE_BITS);
    for (;;) {
        unsigned cur = g_keys[h];
        if (cur == key) return h;
        if (cur == 0u) {
            unsigned prev = atomicCAS(&g_keys[h], 0u, key);
            if (prev == 0u || prev == key) return h;
        }
        h = (h + 1u) & TABLE_MASK;
    }
}

__device__ __forceinline__ unsigned hash_find(unsigned key) {
    unsigned h = (key * 2654435761u) >> (32 - TABLE_BITS);
    while (g_keys[h] != key) h = (h + 1u) & TABLE_MASK;
    return h;
}

// Packed (score, index) key — ONE definition so pass1/pass3 agree bit-exactly.
__device__ __forceinline__ unsigned long long pack_key(float c, float o,
                                                       unsigned p) {
    float score = __fmaf_rn(CONF_W, c, __fmul_rn(OPAC_W, o));
    return ((unsigned long long)__float_as_uint(score) << 32)
         | (unsigned long long)(0xFFFFFFFFu - p);
}

template <bool CLAIM>
__device__ __forceinline__ unsigned cell_slot(int b, int vx, int vy, int vz) {
    unsigned ux = (unsigned)(vx - WIN_LO);
    unsigned uy = (unsigned)(vy - WIN_LO);
    unsigned uz = (unsigned)(vz - WIN_LO);
    if ((ux < WIN_SZ) & (uy < WIN_SZ) & (uz < WIN_SZ)) {
        return (((unsigned)b * WIN_SZ + ux) * WIN_SZ + uy) * WIN_SZ + uz;
    }
    unsigned vid = ((unsigned)vx << 20) | ((unsigned)vy << 10) | (unsigned)vz;
    unsigned key = 0x80000000u | ((unsigned)b << 30) | vid;   // never 0
    unsigned h = CLAIM ? hash_claim(key) : hash_find(key);
    return (unsigned)DIRECT_SLOTS + h;
}

// Proven-numerics geometry from the pixel coordinates (same expressions as R6).
__device__ __forceinline__ void point_geom(
    int b, int n, int h, int w, float d, const float* __restrict__ poses,
    float& mx, float& my, float& mz, int& vx, int& vy, int& vz)
{
    const float fx = (float)((double)WW / (2.0 * M_PI));
    const float fy = (float)(-(double)HH / M_PI);
    float lon = ((float)w + 0.5f - (float)(WW / 2)) / fx;
    float lat = ((float)h + 0.5f - (float)(HH / 2)) / fy;
    float slat, clat, slon, clon;
    sincosf(lat, &slat, &clat);
    sincosf(lon, &slon, &clon);
    float dx = clat * slon;
    float dy = -slat;
    float dz = clat * clon;

    float px = d * dx, py = d * dy, pz = d * dz;

    const float* M = poses + (size_t)(b * NV + n) * 16;
    mx = M[0] * px + M[1] * py + M[2]  * pz + M[3];
    my = M[4] * px + M[5] * py + M[6]  * pz + M[7];
    mz = M[8] * px + M[9] * py + M[10] * pz + M[11];

    vx = min(max((int)floorf(mx / VOXEL_SIZE) + 512, 0), 1023);
    vy = min(max((int)floorf(my / VOXEL_SIZE) + 512, 0), 1023);
    vz = min(max((int)floorf(mz / VOXEL_SIZE) + 512, 0), 1023);
}

// pass1, software-pipelined: Phase A computes slots/keys for 4 points without
// branches; Phase B issues all 4 random 16B snapshot loads back-to-back (the
// ~250-cycle L2 latencies overlap); Phase C does the pruned atomic sequence
// for the ~30% of points that survive the monotonic-snapshot test.
__global__ void __launch_bounds__(256) pass1_kernel(
    const float* __restrict__ depth, const float* __restrict__ opac,
    const float* __restrict__ conf,  const float* __restrict__ poses)
{
    int q = blockIdx.x * blockDim.x + threadIdx.x;   // grid exact: TOTAL/1024
    int g0 = q << 2;

    int b   = g0 / PP;
    int p0  = g0 - b * PP;
    int n   = p0 / HWSZ;
    int hw0 = p0 - n * HWSZ;
    int h   = hw0 / WW;
    int w0  = hw0 - h * WW;

    float4 d4 = *reinterpret_cast<const float4*>(depth + g0);
    float4 c4 = *reinterpret_cast<const float4*>(conf  + g0);
    float4 o4 = *reinterpret_cast<const float4*>(opac  + g0);
    float dd[4] = {d4.x, d4.y, d4.z, d4.w};
    float cc[4] = {c4.x, c4.y, c4.z, c4.w};
    float oo[4] = {o4.x, o4.y, o4.z, o4.w};

    // Phase A: slots + packed keys, branch-free (invalid -> slot 0, pk 0).
    unsigned slots[4];
    unsigned long long pks[4];
    bool vals[4];
#pragma unroll
    for (int k = 0; k < 4; k++) {
        float c = cc[k], o = oo[k];
        bool valid = (c > CONF_THRESH) && (o > OPAC_THRESH);
        vals[k] = valid;
        float mx, my, mz; int vx, vy, vz;
        point_geom(b, n, h, w0 + k, dd[k], poses, mx, my, mz, vx, vy, vz);
        slots[k] = valid ? cell_slot<true>(b, vx, vy, vz) : 0u;
        pks[k]   = valid ? pack_key(c, o, (unsigned)(p0 + k)) : 0ull;
    }

    // Phase B: batch the 4 independent snapshot loads (overlapping latency).
    ulonglong2 snaps[4];
#pragma unroll
    for (int k = 0; k < 4; k++)
        snaps[k] = g_pair[slots[k]];

    // Phase C: pruned streaming top-2 (R15-proven semantics).
#pragma unroll
    for (int k = 0; k < 4; k++) {
        if (!vals[k]) continue;
        unsigned long long pk = pks[k];
        ulonglong2 snap = snaps[k];
        // Monotone non-decreasing values -> stale reads are SAFE:
        //   pk <= snap.m2  =>  final m2 >= snap.m2 >= pk  => no effect.
        if (pk <= snap.y) continue;                 // zero atomics

        unsigned slot = slots[k];
        unsigned long long* m1 =
            &reinterpret_cast<unsigned long long*>(g_pair)[2 * (size_t)slot];
        unsigned long long old = atomicMax(m1, pk);
        if (old == 0ull) {                          // first toucher records
            unsigned idx = atomicAdd(&g_cnt, 1u);
            g_used[idx] = slot;
        }
        unsigned long long v = (pk < old) ? pk : old;   // displaced value
        if (v > snap.y)                             // same monotonic argument
            atomicMax(m1 + 1, v);                   // result unused -> RED
    }
}

// pass3: compute selection FIRST; ~94% of rows are feat*0 == 0, so the 19
// feature-channel reads are skipped for unselected points (R13-proven).
__global__ void __launch_bounds__(256) pass3_kernel(
    const float* __restrict__ depth, const float* __restrict__ cov,
    const float* __restrict__ rot,   const float* __restrict__ opac,
    const float* __restrict__ sh,    const float* __restrict__ conf,
    const float* __restrict__ poses, float* __restrict__ out,
    int write_sel, size_t sel_off)
{
    int g = blockIdx.x * blockDim.x + threadIdx.x;
    if (g >= TOTAL) return;

    int b  = g / PP;
    int p  = g - b * PP;
    int n  = p / HWSZ;
    int hw = p - n * HWSZ;
    int h  = hw / WW;
    int w  = hw - h * WW;

    float d = depth[g];
    float c = conf[g];
    float o = opac[g];
    bool valid = (c > CONF_THRESH) && (o > OPAC_THRESH);

    float mx, my, mz; int vx, vy, vz;
    point_geom(b, n, h, w, d, poses, mx, my, mz, vx, vy, vz);

    bool sel = false;
    if (valid) {
        unsigned slot = cell_slot<false>(b, vx, vy, vz);
        unsigned long long packed = pack_key(c, o, (unsigned)p);
        ulonglong2 pr = __ldg(&g_pair[slot]);
        sel = (packed == pr.x || packed == pr.y);
    }

    float4* dst = reinterpret_cast<float4*>(out + (size_t)g * NCH);
    if (!sel) {
        float4 z = make_float4(0.f, 0.f, 0.f, 0.f);
#pragma unroll
        for (int i = 0; i < 6; i++)
            __stcs(dst + i, z);
    } else {
        size_t bn     = (size_t)(b * NV + n);
        size_t base_c = (bn * 3)  * HWSZ + hw;
        size_t base_r = (bn * 4)  * HWSZ + hw;
        size_t base_s = (bn * 12) * HWSZ + hw;

        float f[NCH];
        f[0] = mx; f[1] = my; f[2] = mz;
        f[3] = __ldcs(&cov[base_c]);
        f[4] = __ldcs(&cov[base_c + HWSZ]);
        f[5] = __ldcs(&cov[base_c + 2 * (size_t)HWSZ]);
#pragma unroll
        for (int i = 0; i < 4; i++)
            f[6 + i] = __ldcs(&rot[base_r + (size_t)i * HWSZ]);
        f[10] = o;
#pragma unroll
        for (int i = 0; i < 12; i++)
            f[11 + i] = __ldcs(&sh[base_s + (size_t)i * HWSZ]);
        f[23] = c;
#pragma unroll
        for (int i = 0; i < 6; i++)
            __stcs(dst + i, make_float4(f[4*i], f[4*i+1], f[4*i+2], f[4*i+3]));
    }

    if (write_sel)
        __stcs(out + sel_off + (size_t)g, sel ? 1.0f : 0.0f);
}

// Zero only the slots touched this launch; restores the pristine zero state
// so the next graph replay starts clean. Last block resets the counters.
#define CLEAN_BLOCKS 512
__global__ void __launch_bounds__(256) cleanup_kernel() {
    unsigned cnt = *(volatile unsigned*)&g_cnt;
    unsigned stride = CLEAN_BLOCKS * 256;
    for (unsigned i = blockIdx.x * 256 + threadIdx.x; i < cnt; i += stride) {
        unsigned slot = g_used[i];
        ulonglong2 z; z.x = 0ull; z.y = 0ull;
        g_pair[slot] = z;
        if (slot >= (unsigned)DIRECT_SLOTS)
            g_keys[slot - (unsigned)DIRECT_SLOTS] = 0u;
    }
    __threadfence();
    if (threadIdx.x == 0) {
        unsigned done = atomicAdd(&g_done, 1u);
        if (done == CLEAN_BLOCKS - 1) {
            g_cnt = 0u;
            g_done = 0u;
            __threadfence();
        }
    }
}

// ---------------------------------------------------------------------------

extern "C" void kernel_launch(void* const* d_in, const int* in_sizes, int n_in,
                              void* d_out, int out_size) {
    const float* depth = (const float*)d_in[0];
    const float* cov   = (const float*)d_in[1];
    const float* rot   = (const float*)d_in[2];
    const float* opac  = (const float*)d_in[3];
    const float* sh    = (const float*)d_in[4];
    const float* conf  = (const float*)d_in[5];
    const float* poses = (const float*)d_in[6];
    float* out = (float*)d_out;

    size_t featN = (size_t)TOTAL * NCH;
    int write_sel = ((size_t)out_size >= featN + (size_t)TOTAL) ? 1 : 0;

    const int T = 256;
    pass1_kernel<<<TOTAL / 4 / T, T>>>(depth, opac, conf, poses);
    pass3_kernel<<<(TOTAL + T - 1) / T, T>>>(depth, cov, rot, opac, sh, conf,
                                             poses, out, write_sel, featN);
    cleanup_kernel<<<CLEAN_BLOCKS, T>>>();
}

// round 17
// speedup vs baseline: 1.0969x; 1.0969x over previous
#include <cuda_runtime.h>
#include <math.h>
#include <stdint.h>

#ifndef M_PI
#define M_PI 3.14159265358979323846
#endif

// Problem shape (fixed by setup_inputs)
#define BB 2
#define NV 4
#define HH 256
#define WW 512
#define HWSZ (HH * WW)            // 131072
#define PP (NV * HWSZ)            // 524288 points per batch
#define TOTAL (BB * PP)           // 1048576 points total
#define NCH 24

#define VOXEL_SIZE 0.1f
#define CONF_W 0.7f
#define OPAC_W 0.3f
#define CONF_THRESH 0.1f
#define OPAC_THRESH 0.01f

// Direct-mapped voxel window: vc in [448, 576) per axis covers |mean|<=6.4,
// far beyond the data's reach. Out-of-window points (practically never) fall
// back to a hash table appended after the direct region -> correct for ANY input.
#define WIN_LO 448
#define WIN_SZ 128
#define DIRECT_SLOTS (BB * WIN_SZ * WIN_SZ * WIN_SZ)   // 4.19M

#define TABLE_BITS 20
#define TABLE_SIZE (1u << TABLE_BITS)
#define TABLE_MASK (TABLE_SIZE - 1u)

#define NSLOTS (DIRECT_SLOTS + (int)TABLE_SIZE)
#define INV_SLOT 0xFFFFFFFFu

// Scratch (__device__ globals, zero-initialized at module load; cleanup
// restores the zero state after every launch so graph replays start clean).
__device__ ulonglong2    g_pair[NSLOTS];            // {max1, max2}, 0 = untouched
__device__ unsigned int  g_keys[TABLE_SIZE];        // fallback hash keys, 0 = empty
__device__ unsigned int  g_used[TOTAL];             // first-touched slot list
__device__ unsigned int  g_cnt;                     // #touched slots
__device__ unsigned int  g_done;                    // cleanup block counter
__device__ unsigned int  g_slotArr[TOTAL];          // 4 MB per-point slot handoff

// ---------------------------------------------------------------------------

__device__ __forceinline__ unsigned hash_claim(unsigned key) {
    unsigned h = (key * 2654435761u) >> (32 - TABLE_BITS);
    for (;;) {
        unsigned cur = g_keys[h];
        if (cur == key) return h;
        if (cur == 0u) {
            unsigned prev = atomicCAS(&g_keys[h], 0u, key);
            if (prev == 0u || prev == key) return h;
        }
        h = (h + 1u) & TABLE_MASK;
    }
}

// Packed (score, index) key — ONE definition so pass1/pass3 agree bit-exactly.
__device__ __forceinline__ unsigned long long pack_key(float c, float o,
                                                       unsigned p) {
    float score = __fmaf_rn(CONF_W, c, __fmul_rn(OPAC_W, o));
    return ((unsigned long long)__float_as_uint(score) << 32)
         | (unsigned long long)(0xFFFFFFFFu - p);
}

__device__ __forceinline__ unsigned cell_slot_claim(int b, int vx, int vy, int vz) {
    unsigned ux = (unsigned)(vx - WIN_LO);
    unsigned uy = (unsigned)(vy - WIN_LO);
    unsigned uz = (unsigned)(vz - WIN_LO);
    if ((ux < WIN_SZ) & (uy < WIN_SZ) & (uz < WIN_SZ)) {
        return (((unsigned)b * WIN_SZ + ux) * WIN_SZ + uy) * WIN_SZ + uz;
    }
    unsigned vid = ((unsigned)vx << 20) | ((unsigned)vy << 10) | (unsigned)vz;
    unsigned key = 0x80000000u | ((unsigned)b << 30) | vid;   // never 0
    return (unsigned)DIRECT_SLOTS + hash_claim(key);
}

// Proven-numerics geometry from the pixel coordinates (same expressions as R6).
__device__ __forceinline__ void point_geom(
    int b, int n, int h, int w, float d, const float* __restrict__ poses,
    float& mx, float& my, float& mz, int& vx, int& vy, int& vz)
{
    const float fx = (float)((double)WW / (2.0 * M_PI));
    const float fy = (float)(-(double)HH / M_PI);
    float lon = ((float)w + 0.5f - (float)(WW / 2)) / fx;
    float lat = ((float)h + 0.5f - (float)(HH / 2)) / fy;
    float slat, clat, slon, clon;
    sincosf(lat, &slat, &clat);
    sincosf(lon, &slon, &clon);
    float dx = clat * slon;
    float dy = -slat;
    float dz = clat * clon;

    float px = d * dx, py = d * dy, pz = d * dz;

    const float* M = poses + (size_t)(b * NV + n) * 16;
    mx = M[0] * px + M[1] * py + M[2]  * pz + M[3];
    my = M[4] * px + M[5] * py + M[6]  * pz + M[7];
    mz = M[8] * px + M[9] * py + M[10] * pz + M[11];

    vx = min(max((int)floorf(mx / VOXEL_SIZE) + 512, 0), 1023);
    vy = min(max((int)floorf(my / VOXEL_SIZE) + 512, 0), 1023);
    vz = min(max((int)floorf(mz / VOXEL_SIZE) + 512, 0), 1023);
}

// pass1: exact R15 structure (4 points/thread, monotonic-snapshot pruning)
// plus ONE extra coalesced uint4 store persisting the per-point slot.
__global__ void __launch_bounds__(256) pass1_kernel(
    const float* __restrict__ depth, const float* __restrict__ opac,
    const float* __restrict__ conf,  const float* __restrict__ poses)
{
    int q = blockIdx.x * blockDim.x + threadIdx.x;   // grid exact: TOTAL/1024
    int g0 = q << 2;

    int b   = g0 / PP;
    int p0  = g0 - b * PP;
    int n   = p0 / HWSZ;
    int hw0 = p0 - n * HWSZ;
    int h   = hw0 / WW;
    int w0  = hw0 - h * WW;

    float4 d4 = *reinterpret_cast<const float4*>(depth + g0);
    float4 c4 = *reinterpret_cast<const float4*>(conf  + g0);
    float4 o4 = *reinterpret_cast<const float4*>(opac  + g0);
    float dd[4] = {d4.x, d4.y, d4.z, d4.w};
    float cc[4] = {c4.x, c4.y, c4.z, c4.w};
    float oo[4] = {o4.x, o4.y, o4.z, o4.w};

    unsigned slots[4];

#pragma unroll
    for (int k = 0; k < 4; k++) {
        float c = cc[k], o = oo[k];
        bool valid = (c > CONF_THRESH) && (o > OPAC_THRESH);
        if (!valid) { slots[k] = INV_SLOT; continue; }

        float mx, my, mz; int vx, vy, vz;
        point_geom(b, n, h, w0 + k, dd[k], poses, mx, my, mz, vx, vy, vz);
        unsigned slot = cell_slot_claim(b, vx, vy, vz);
        slots[k] = slot;
        unsigned long long pk = pack_key(c, o, (unsigned)(p0 + k));

        // Snapshot (plain L2 read). Values are monotone non-decreasing ->
        // stale reads are SAFE: pk <= snap.m2 => final m2 >= pk => no effect.
        ulonglong2 snap = g_pair[slot];
        if (pk <= snap.y) continue;                 // zero atomics

        unsigned long long* m1 =
            &reinterpret_cast<unsigned long long*>(g_pair)[2 * (size_t)slot];
        unsigned long long old = atomicMax(m1, pk);
        if (old == 0ull) {                          // first toucher records
            unsigned idx = atomicAdd(&g_cnt, 1u);
            g_used[idx] = slot;
        }
        unsigned long long v = (pk < old) ? pk : old;   // displaced value
        if (v > snap.y)                             // same monotonic argument
            atomicMax(m1 + 1, v);                   // result unused -> RED
    }

    *reinterpret_cast<uint4*>(g_slotArr + g0) =
        make_uint4(slots[0], slots[1], slots[2], slots[3]);
}

// pass3: selection from persisted slot + cheap pack_key(conf, opac) — no
// trig/pose/depth work for the ~94% unselected points. Geometry + channel
// gather only when selected (bit-identical means via point_geom).
__global__ void __launch_bounds__(256) pass3_kernel(
    const float* __restrict__ depth, const float* __restrict__ cov,
    const float* __restrict__ rot,   const float* __restrict__ opac,
    const float* __restrict__ sh,    const float* __restrict__ conf,
    const float* __restrict__ poses, float* __restrict__ out,
    int write_sel, size_t sel_off)
{
    int g = blockIdx.x * blockDim.x + threadIdx.x;
    if (g >= TOTAL) return;

    int b = g / PP;
    int p = g - b * PP;

    unsigned slot = g_slotArr[g];
    float c = conf[g];
    float o = opac[g];

    bool sel = false;
    if (slot != INV_SLOT) {
        unsigned long long packed = pack_key(c, o, (unsigned)p);
        ulonglong2 pr = __ldg(&g_pair[slot]);
        sel = (packed == pr.x || packed == pr.y);
    }

    float4* dst = reinterpret_cast<float4*>(out + (size_t)g * NCH);
    if (!sel) {
        float4 z = make_float4(0.f, 0.f, 0.f, 0.f);
#pragma unroll
        for (int i = 0; i < 6; i++)
            __stcs(dst + i, z);
    } else {
        int n  = p / HWSZ;
        int hw = p - n * HWSZ;
        int h  = hw / WW;
        int w  = hw - h * WW;

        float d = depth[g];
        float mx, my, mz; int vx, vy, vz;
        point_geom(b, n, h, w, d, poses, mx, my, mz, vx, vy, vz);

        size_t bn     = (size_t)(b * NV + n);
        size_t base_c = (bn * 3)  * HWSZ + hw;
        size_t base_r = (bn * 4)  * HWSZ + hw;
        size_t base_s = (bn * 12) * HWSZ + hw;

        float f[NCH];
        f[0] = mx; f[1] = my; f[2] = mz;
        f[3] = __ldcs(&cov[base_c]);
        f[4] = __ldcs(&cov[base_c + HWSZ]);
        f[5] = __ldcs(&cov[base_c + 2 * (size_t)HWSZ]);
#pragma unroll
        for (int i = 0; i < 4; i++)
            f[6 + i] = __ldcs(&rot[base_r + (size_t)i * HWSZ]);
        f[10] = o;
#pragma unroll
        for (int i = 0; i < 12; i++)
            f[11 + i] = __ldcs(&sh[base_s + (size_t)i * HWSZ]);
        f[23] = c;
#pragma unroll
        for (int i = 0; i < 6; i++)
            __stcs(dst + i, make_float4(f[4*i], f[4*i+1], f[4*i+2], f[4*i+3]));
    }

    if (write_sel)
        __stcs(out + sel_off + (size_t)g, sel ? 1.0f : 0.0f);
}

// Zero only the slots touched this launch; restores the pristine zero state
// so the next graph replay starts clean. Last block resets the counters.
#define CLEAN_BLOCKS 512
__global__ void __launch_bounds__(256) cleanup_kernel() {
    unsigned cnt = *(volatile unsigned*)&g_cnt;
    unsigned stride = CLEAN_BLOCKS * 256;
    for (unsigned i = blockIdx.x * 256 + threadIdx.x; i < cnt; i += stride) {
        unsigned slot = g_used[i];
        ulonglong2 z; z.x = 0ull; z.y = 0ull;
        g_pair[slot] = z;
        if (slot >= (unsigned)DIRECT_SLOTS)
            g_keys[slot - (unsigned)DIRECT_SLOTS] = 0u;
    }
    __threadfence();
    if (threadIdx.x == 0) {
        unsigned done = atomicAdd(&g_done, 1u);
        if (done == CLEAN_BLOCKS - 1) {
            g_cnt = 0u;
            g_done = 0u;
            __threadfence();
        }
    }
}

// ---------------------------------------------------------------------------

extern "C" void kernel_launch(void* const* d_in, const int* in_sizes, int n_in,
                              void* d_out, int out_size) {
    const float* depth = (const float*)d_in[0];
    const float* cov   = (const float*)d_in[1];
    const float* rot   = (const float*)d_in[2];
    const float* opac  = (const float*)d_in[3];
    const float* sh    = (const float*)d_in[4];
    const float* conf  = (const float*)d_in[5];
    const float* poses = (const float*)d_in[6];
    float* out = (float*)d_out;

    size_t featN = (size_t)TOTAL * NCH;
    int write_sel = ((size_t)out_size >= featN + (size_t)TOTAL) ? 1 : 0;

    const int T = 256;
    pass1_kernel<<<TOTAL / 4 / T, T>>>(depth, opac, conf, poses);
    pass3_kernel<<<(TOTAL + T - 1) / T, T>>>(depth, cov, rot, opac, sh, conf,
                                             poses, out, write_sel, featN);
    cleanup_kernel<<<CLEAN_BLOCKS, T>>>();
}